// round 10
// baseline (speedup 1.0000x reference)
#include <cuda_runtime.h>
#include <math.h>

#define PS 32
#define NB 36
#define NBH 37                 // hist bins incl. the obig==36.0 edge (folded into 0 later)
#define WPB 8
#define THREADS (WPB * 32)
#define NCOPY 32               // one private hist copy per lane

typedef unsigned long long u64p;

__device__ __forceinline__ u64p pk(float lo, float hi) {
    u64p r; asm("mov.b64 %0, {%1, %2};" : "=l"(r) : "f"(lo), "f"(hi)); return r;
}
__device__ __forceinline__ void upk(u64p v, float& lo, float& hi) {
    asm("mov.b64 {%0, %1}, %2;" : "=f"(lo), "=f"(hi) : "l"(v));
}
__device__ __forceinline__ u64p add2(u64p a, u64p b) {
    u64p r; asm("add.rn.f32x2 %0, %1, %2;" : "=l"(r) : "l"(a), "l"(b)); return r;
}
__device__ __forceinline__ u64p mul2(u64p a, u64p b) {
    u64p r; asm("mul.rn.f32x2 %0, %1, %2;" : "=l"(r) : "l"(a), "l"(b)); return r;
}
__device__ __forceinline__ u64p fma2(u64p a, u64p b, u64p c) {
    u64p r; asm("fma.rn.f32x2 %0, %1, %2, %3;" : "=l"(r) : "l"(a), "l"(b), "l"(c)); return r;
}

#define PKC(v) ((((u64p)__float_as_uint(v)) << 32) | (u64p)__float_as_uint(v))

__global__ __launch_bounds__(THREADS, 5)
void orient_kernel(const float* __restrict__ x,
                   const float* __restrict__ gk,
                   float* __restrict__ out,
                   int B, float c_hi, float c_lo)
{
    __shared__ float s_gk[PS * PS];                       // staged as 0.5 * gk
    __shared__ __align__(8) float s_priv[WPB][NBH * NCOPY];
    __shared__ float s_hist[WPB][40];
    __shared__ float s_sm[WPB][40];

    const int tid   = threadIdx.x;
    const int w     = tid >> 5;
    const int lane  = tid & 31;
    const int patch = blockIdx.x * WPB + w;
    const bool valid = (patch < B);

    for (int i = tid; i < PS * PS; i += THREADS) s_gk[i] = 0.5f * gk[i];

    float* priv = s_priv[w];
    {   // packed zeroing: NBH*NCOPY floats = 592 u64 per warp
        u64p* pz = (u64p*)priv;
        #pragma unroll
        for (int i = lane; i < (NBH * NCOPY) / 2; i += 32) pz[i] = 0ull;
    }
    __syncthreads();

    const float PI_F  = 3.14159265358979323846f;
    const float TPI_F = 6.28318530717958647692f;
    const unsigned FULL = 0xffffffffu;

    const u64p NEG12 = PKC(-1.0f);
    const u64p EPS42 = PKC(4e-10f);          // 4 * 1e-10 (grad scale absorbed)

    const int h    = lane >> 4;              // row-half
    const int hl   = lane & 15;              // column-pair index
    const int col0 = 2 * hl;

    const float* xp = x + (size_t)(valid ? patch : 0) * (PS * PS);
    const float* xh = xp + h * 16 * PS;
    const int gkb   = h * 16 * PS + col0;

    float2 cur = *(const float2*)(xh + col0);
    float2 prv = (h == 0) ? cur : *(const float2*)(xh - PS + col0);
    float2 nxt = *(const float2*)(xh + PS + col0);

    #pragma unroll
    for (int r = 0; r < 16; r++) {
        float Lup = __shfl_up_sync(FULL, cur.y, 1, 16);
        float Rdn = __shfl_down_sync(FULL, cur.x, 1, 16);
        float left0  = (hl == 0)  ? cur.x : Lup;
        float right1 = (hl == 15) ? cur.y : Rdn;

        // Unscaled gradients, packed (atan2f bit-invariant to exact 0.5 scale)
        u64p prv2 = pk(prv.x, prv.y);
        u64p nxt2 = pk(nxt.x, nxt.y);
        u64p dy2  = fma2(nxt2, NEG12, prv2);              // prv - nxt
        u64p ga   = pk(left0, cur.x);
        u64p gb   = pk(cur.y, right1);
        u64p dx2  = fma2(gb, NEG12, ga);                  // left - right

        float dx0, dx1, dy0, dy1;
        upk(dx2, dx0, dx1);
        upk(dy2, dy0, dy1);

        // packed magnitude path (continuous)
        u64p m2v  = fma2(dx2, dx2, fma2(dy2, dy2, EPS42));
        float m20, m21; upk(m2v, m20, m21);
        u64p rs2  = pk(rsqrtf(m20), rsqrtf(m21));
        u64p gk2  = *(const u64p*)(s_gk + gkb + r * PS);  // LDS.64 (0.5*gk)
        u64p mag2 = mul2(mul2(m2v, rs2), gk2);
        float mag0, mag1; upk(mag2, mag0, mag1);

        // FROZEN chain, scalar (identical IEEE-rn ops; no pack/unpack MOVs)
        float ori0 = atan2f(dy0, dx0);
        float ori1 = atan2f(dy1, dx1);
        float t0 = __fmul_rn(36.0f, __fadd_rn(ori0, PI_F));
        float t1 = __fmul_rn(36.0f, __fadd_rn(ori1, PI_F));
        float obig0 = fmaf(t0, c_hi, __fmul_rn(t0, c_lo));  // == __fdiv_rn(t0, TPI_F)
        float obig1 = fmaf(t1, c_hi, __fmul_rn(t1, c_lo));
        float bo00 = floorf(obig0);
        float bo01 = floorf(obig1);
        int bx = (int)bo00;                  // 0..36, NO wrap (37-bin hist)
        int by = (int)bo01;
        float wo10 = __fsub_rn(obig0, bo00);
        float wo11 = __fsub_rn(obig1, bo01);
        float wx = fmaf(-wo10, mag0, mag0);  // (1-wo1)*mag
        float wy = fmaf(-wo11, mag1, mag1);

        // per-lane private hist: bank == lane, no conflicts, no races
        priv[bx * NCOPY + lane] += wx;
        priv[by * NCOPY + lane] += wy;

        prv = cur;
        cur = nxt;
        if (r < 15) {
            if (r < 14 || h == 0) nxt = *(const float2*)(xh + (r + 2) * PS + col0);
            else                  nxt = cur;
        }
    }
    __syncwarp();

    // fold bin 36 (obig==36.0 edge) into bin 0: packed, conflict-free
    if (lane < 16) {
        u64p* p0 = (u64p*)priv;                    // bin 0, u64 index lane
        u64p* p36 = (u64p*)(priv + 36 * NCOPY);
        p0[lane] = add2(p0[lane], p36[lane]);
    }
    __syncwarp();

    // reduce 32 copies -> 36 bins with packed LDS.64 (rotated, 2-way max)
    u64p acc1 = 0ull;
    #pragma unroll
    for (int c = 0; c < 16; c++) {
        int cc0 = 2 * ((c + lane) & 15);
        acc1 = add2(acc1, *(const u64p*)(priv + lane * NCOPY + cc0));
    }
    float a1lo, a1hi; upk(acc1, a1lo, a1hi);
    float s1 = a1lo + a1hi;

    const int l2 = 32 + (lane & 3);
    u64p acc2 = 0ull;
    #pragma unroll
    for (int c = 0; c < 16; c++) {
        int cc0 = 2 * ((c + lane) & 15);
        acc2 = add2(acc2, *(const u64p*)(priv + l2 * NCOPY + cc0));
    }
    float a2lo, a2hi; upk(acc2, a2lo, a2hi);
    float s2 = a2lo + a2hi;

    s_hist[w][lane] = s1;
    if (lane < 4) s_hist[w][32 + lane] = s2;
    __syncwarp();

    // zero-padded smoothing [0.33, 0.34, 0.33]
    {
        float h0 = s_hist[w][lane];
        float hm = (lane > 0) ? s_hist[w][lane - 1] : 0.0f;
        float hp = s_hist[w][lane + 1];
        float a  = __fmul_rn(0.33f, hm);
        float bb = __fmul_rn(0.34f, h0);
        float c  = __fmul_rn(0.33f, hp);
        s_sm[w][lane] = __fadd_rn(__fadd_rn(a, bb), c);
    }
    if (lane < 4) {
        int i = 32 + lane;
        float h0 = s_hist[w][i];
        float hm = s_hist[w][i - 1];
        float hp = (i < NB - 1) ? s_hist[w][i + 1] : 0.0f;
        float a  = __fmul_rn(0.33f, hm);
        float bb = __fmul_rn(0.34f, h0);
        float c  = __fmul_rn(0.33f, hp);
        s_sm[w][i] = __fadd_rn(__fadd_rn(a, bb), c);
    }
    __syncwarp();

    if (lane == 0 && valid) {
        float best = s_sm[w][0];
        int   bi   = 0;
        #pragma unroll
        for (int i = 1; i < NB; i++) {
            float v = s_sm[w][i];
            if (v > best) { best = v; bi = i; }
        }
        float ang = __fsub_rn(__fdiv_rn(__fmul_rn(TPI_F, (float)bi), (float)NB), PI_F);
        out[patch] = -ang;
    }
}

extern "C" void kernel_launch(void* const* d_in, const int* in_sizes, int n_in,
                              void* d_out, int out_size)
{
    const float* x  = (const float*)d_in[0];
    const float* gk = (const float*)d_in[1];
    float* out = (float*)d_out;
    int B = in_sizes[0] / (PS * PS);
    int nblocks = (B + WPB - 1) / WPB;

    const float TPI_F = 6.28318530717958647692f;
    double inv = 1.0 / (double)TPI_F;
    float c_hi = (float)inv;
    float c_lo = (float)(inv - (double)c_hi);

    orient_kernel<<<nblocks, THREADS>>>(x, gk, out, B, c_hi, c_lo);
}

// round 11
// speedup vs baseline: 1.0700x; 1.0700x over previous
#include <cuda_runtime.h>
#include <math.h>

#define PS 32
#define NB 36
#define WPB 8
#define THREADS (WPB * 32)
#define NCOPY 32               // one private hist copy per lane

typedef unsigned long long u64p;

__device__ __forceinline__ u64p pk(float lo, float hi) {
    u64p r; asm("mov.b64 %0, {%1, %2};" : "=l"(r) : "f"(lo), "f"(hi)); return r;
}
__device__ __forceinline__ void upk(u64p v, float& lo, float& hi) {
    asm("mov.b64 {%0, %1}, %2;" : "=f"(lo), "=f"(hi) : "l"(v));
}
__device__ __forceinline__ u64p add2(u64p a, u64p b) {
    u64p r; asm("add.rn.f32x2 %0, %1, %2;" : "=l"(r) : "l"(a), "l"(b)); return r;
}
__device__ __forceinline__ u64p mul2(u64p a, u64p b) {
    u64p r; asm("mul.rn.f32x2 %0, %1, %2;" : "=l"(r) : "l"(a), "l"(b)); return r;
}
__device__ __forceinline__ u64p fma2(u64p a, u64p b, u64p c) {
    u64p r; asm("fma.rn.f32x2 %0, %1, %2, %3;" : "=l"(r) : "l"(a), "l"(b), "l"(c)); return r;
}

#define PKC(v) ((((u64p)__float_as_uint(v)) << 32) | (u64p)__float_as_uint(v))

__global__ __launch_bounds__(THREADS, 6)
void orient_kernel(const float* __restrict__ x,
                   const float* __restrict__ gk,
                   float* __restrict__ out,
                   int B, float c_hi, float c_lo)
{
    // ONLY smem: per-warp private hist (also reused as hist/sm scratch)
    __shared__ __align__(8) float s_priv[WPB][NB * NCOPY];

    const int tid   = threadIdx.x;
    const int w     = tid >> 5;
    const int lane  = tid & 31;
    const int patch = blockIdx.x * WPB + w;
    const bool valid = (patch < B);

    float* priv = s_priv[w];
    {   // packed zeroing: NB*NCOPY floats = 576 u64 per warp
        u64p* pz = (u64p*)priv;
        #pragma unroll
        for (int i = lane; i < (NB * NCOPY) / 2; i += 32) pz[i] = 0ull;
    }
    __syncwarp();              // priv is warp-private: no block barrier needed

    const float PI_F  = 3.14159265358979323846f;
    const float TPI_F = 6.28318530717958647692f;
    const unsigned FULL = 0xffffffffu;

    const u64p NEG12 = PKC(-1.0f);
    const u64p PI2   = PKC(PI_F);
    const u64p C362  = PKC(36.0f);
    const u64p EPS42 = PKC(4e-10f);          // 4 * 1e-10 (grad scale absorbed)
    const u64p HALF2 = PKC(0.5f);
    const u64p NEGH2 = PKC(-0.5f);
    const u64p CHI2  = PKC(c_hi);
    const u64p CLO2  = PKC(c_lo);

    const int h    = lane >> 4;              // row-half
    const int hl   = lane & 15;              // column-pair index
    const int col0 = 2 * hl;

    const float* xp = x + (size_t)(valid ? patch : 0) * (PS * PS);
    const float* xh = xp + h * 16 * PS;
    const float* gkh = gk + h * 16 * PS + col0;   // unscaled gk, read via L1

    float2 cur = *(const float2*)(xh + col0);
    float2 prv = (h == 0) ? cur : *(const float2*)(xh - PS + col0);
    float2 nxt = *(const float2*)(xh + PS + col0);

    #pragma unroll
    for (int r = 0; r < 16; r++) {
        float Lup = __shfl_up_sync(FULL, cur.y, 1, 16);
        float Rdn = __shfl_down_sync(FULL, cur.x, 1, 16);
        float left0  = (hl == 0)  ? cur.x : Lup;
        float right1 = (hl == 15) ? cur.y : Rdn;

        // Unscaled gradients (atan2f bit-invariant to exact 0.5 scaling)
        u64p prv2 = pk(prv.x, prv.y);
        u64p nxt2 = pk(nxt.x, nxt.y);
        u64p dy2  = fma2(nxt2, NEG12, prv2);              // prv - nxt
        u64p ga   = pk(left0, cur.x);
        u64p gb   = pk(cur.y, right1);
        u64p dx2  = fma2(gb, NEG12, ga);                  // left - right

        float dx0, dx1, dy0, dy1;
        upk(dx2, dx0, dx1);
        upk(dy2, dy0, dy1);

        // FROZEN: libdevice atan2f (bit-exact vs XLA)
        float ori0 = atan2f(dy0, dx0);
        float ori1 = atan2f(dy1, dx1);

        // FROZEN chain: t36 = RN(36*RN(ori+pi)); obig = RN(t36/TPI_F) via
        // correctly-rounded double-float multiply
        u64p t36   = mul2(add2(pk(ori0, ori1), PI2), C362);
        u64p obig2 = fma2(t36, CHI2, mul2(t36, CLO2));
        float obig0, obig1; upk(obig2, obig0, obig1);
        float bo00 = floorf(obig0);
        float bo01 = floorf(obig1);
        int bx = (int)bo00; if (bx >= NB) bx -= NB;
        int by = (int)bo01; if (by >= NB) by -= NB;

        // continuous path: mag = sqrt(dx^2+dy^2+4e-10) * gk ; the reference's
        // 0.5 grad scale is folded into the (0.5 - 0.5*wo1) weight below.
        u64p wo2  = fma2(pk(bo00, bo01), NEG12, obig2);
        u64p m2v  = fma2(dx2, dx2, fma2(dy2, dy2, EPS42));
        float m20, m21; upk(m2v, m20, m21);
        u64p rs2  = pk(rsqrtf(m20), rsqrtf(m21));
        float2 gkv = __ldg((const float2*)(gkh + r * PS)); // L1-resident 4KB
        u64p mag2 = mul2(mul2(m2v, rs2), pk(gkv.x, gkv.y));
        u64p wv2  = mul2(fma2(wo2, NEGH2, HALF2), mag2);   // (1-wo1)*0.5*mag
        float wx, wy; upk(wv2, wx, wy);

        // per-lane private hist: bank == lane, no conflicts, no races
        priv[bx * NCOPY + lane] += wx;
        priv[by * NCOPY + lane] += wy;

        prv = cur;
        cur = nxt;
        if (r < 15) {
            if (r < 14 || h == 0) nxt = *(const float2*)(xh + (r + 2) * PS + col0);
            else                  nxt = cur;
        }
    }
    __syncwarp();

    // reduce 32 copies -> 36 bins with packed LDS.64 (rotated, 2-way max)
    u64p acc1 = 0ull;
    #pragma unroll
    for (int c = 0; c < 16; c++) {
        int cc0 = 2 * ((c + lane) & 15);
        acc1 = add2(acc1, *(const u64p*)(priv + lane * NCOPY + cc0));
    }
    float a1lo, a1hi; upk(acc1, a1lo, a1hi);
    float s1 = a1lo + a1hi;

    const int l2 = 32 + (lane & 3);
    u64p acc2 = 0ull;
    #pragma unroll
    for (int c = 0; c < 16; c++) {
        int cc0 = 2 * ((c + lane) & 15);
        acc2 = add2(acc2, *(const u64p*)(priv + l2 * NCOPY + cc0));
    }
    float a2lo, a2hi; upk(acc2, a2lo, a2hi);
    float s2 = a2lo + a2hi;
    __syncwarp();                      // all reduction reads of priv done

    // reuse priv: hist at priv[0..35], smoothed at priv[64..99]
    priv[lane] = s1;
    if (lane < 4) priv[32 + lane] = s2;
    __syncwarp();

    {
        float h0 = priv[lane];
        float hm = (lane > 0) ? priv[lane - 1] : 0.0f;
        float hp = priv[lane + 1];
        float a  = __fmul_rn(0.33f, hm);
        float bb = __fmul_rn(0.34f, h0);
        float c  = __fmul_rn(0.33f, hp);
        priv[64 + lane] = __fadd_rn(__fadd_rn(a, bb), c);
    }
    if (lane < 4) {
        int i = 32 + lane;
        float h0 = priv[i];
        float hm = priv[i - 1];
        float hp = (i < NB - 1) ? priv[i + 1] : 0.0f;
        float a  = __fmul_rn(0.33f, hm);
        float bb = __fmul_rn(0.34f, h0);
        float c  = __fmul_rn(0.33f, hp);
        priv[64 + i] = __fadd_rn(__fadd_rn(a, bb), c);
    }
    __syncwarp();

    if (lane == 0 && valid) {
        float best = priv[64];
        int   bi   = 0;
        #pragma unroll
        for (int i = 1; i < NB; i++) {
            float v = priv[64 + i];
            if (v > best) { best = v; bi = i; }
        }
        float ang = __fsub_rn(__fdiv_rn(__fmul_rn(TPI_F, (float)bi), (float)NB), PI_F);
        out[patch] = -ang;
    }
}

extern "C" void kernel_launch(void* const* d_in, const int* in_sizes, int n_in,
                              void* d_out, int out_size)
{
    const float* x  = (const float*)d_in[0];
    const float* gk = (const float*)d_in[1];
    float* out = (float*)d_out;
    int B = in_sizes[0] / (PS * PS);
    int nblocks = (B + WPB - 1) / WPB;

    const float TPI_F = 6.28318530717958647692f;
    double inv = 1.0 / (double)TPI_F;
    float c_hi = (float)inv;
    float c_lo = (float)(inv - (double)c_hi);

    orient_kernel<<<nblocks, THREADS>>>(x, gk, out, B, c_hi, c_lo);
}